// round 12
// baseline (speedup 1.0000x reference)
#include <cuda_runtime.h>
#include <cuda_bf16.h>
#include <cstdint>

// OTAM cumulative soft-min DP.  dists: [200,200,32,32] f32 -> out [200,200] f32.
// lambda = 0.5.  Exp-domain: E(l,m) = 2^(S - v(l,m)/(lambda*ln2)), S = 96.
//   interior: E = w*(left + diag),  w = 2^(-d*C2)   (one FFMA on-chain)
//   m==1:     E = w*(2^(S+1) + above)
//   m==33:    E = left + diag + above               (d=0 -> w=1)
//   row 0:    E[m] = E[m-1]*w_m,  E[33] = E[32]
//   out = lambda*ln2 * (S - log2(E(31,33)))
//
// Round-12: 1KB DRAM bursts. Stage = 8 rows (1KB per problem, contiguous),
// double-buffered, 1-warp CTAs (32 problems each). 66.6KB smem -> 3 CTAs/SM.
// Tests the hypothesis that the 4.9TB/s plateau is HBM row-activation
// inefficiency from 256-512B chunked reads.

#define QTOT 40000
#define PPW 32                     // problems per warp (= per block)
#define CHUNK_WORDS 260            // 8 rows * 32 floats + 4 pad (65 f4 = 1 mod 8)
#define BUF_WORDS_1 (PPW * CHUNK_WORDS)    // 8320 floats = 33280 B
#define SMEM_WORDS (2 * BUF_WORDS_1)       // 16640 floats = 66560 B

__device__ __forceinline__ float ex2f(float x) {
    float y; asm("ex2.approx.f32 %0, %1;" : "=f"(y) : "f"(x)); return y;
}
__device__ __forceinline__ float lg2f(float x) {
    float y; asm("lg2.approx.f32 %0, %1;" : "=f"(y) : "f"(x)); return y;
}
__device__ __forceinline__ void cp_async16(unsigned int dst, const void* src) {
    asm volatile("cp.async.cg.shared.global [%0], [%1], 16;\n"
                 :: "r"(dst), "l"(src) : "memory");
}

#define ELT4(v, k) ((k)==0 ? (v).x : ((k)==1 ? (v).y : ((k)==2 ? (v).z : (v).w)))

#define NC2    (-2.8853900817779268f)   // -1/(lambda*ln2)
#define LLN2   (0.34657359027997264f)   // lambda*ln2
#define TWO_S  (7.922816251426434e28f)  // 2^96
#define TWO_S2 (1.5845632502852868e29f) // 2^97
#define SLLN2  (33.271064666877374f)    // 96 * lambda*ln2

// Two skewed rows (A above B, B one column behind), exp domain, with a
// one-step-delayed prev[] write so the in-place update is hazard-free.
// ch: 64 floats = d-values of rows A (ch[0..31]) and B (ch[32..63]).
__device__ __forceinline__ void two_rows(const float* __restrict__ ch, float* prev) {
    const float* dA = ch;        // upper row's 32 d-values
    const float* dB = ch + 32;   // lower row
    float4 qA, qB;
    float cumA = TWO_S, cumPA = TWO_S, cumB = TWO_S;
    float wpend = 0.0f;

    #pragma unroll
    for (int t = 1; t <= 34; t++) {
        if (t >= 3) prev[t - 2] = wpend;          // delayed write of B's col t-2

        if (t >= 2) {                             // row B: m = t-1
            const int m = t - 1, j = m - 1;
            if (j < 32 && (j & 3) == 0) qB = *reinterpret_cast<const float4*>(dB + j);
            float v;
            if (m == 1) {
                const float w = ex2f(qB.x * NC2);
                v = w * (TWO_S2 + cumA);          // left=diag=2^S, above=v(A,1)
            } else if (m == 33) {
                v = cumB + cumPA + cumA;          // left + diag + above, w=1
            } else {
                const float w = ex2f(ELT4(qB, j & 3) * NC2);
                v = fmaf(w, cumB, w * cumPA);
            }
            wpend = v;
            cumB  = v;
        }

        if (t <= 33) {                            // row A: m = t
            const int m = t, j = m - 1;
            if ((j & 3) == 0) qA = *reinterpret_cast<const float4*>(dA + j);
            float v;
            if (m == 1) {
                const float w = ex2f(qA.x * NC2);
                v = w * (TWO_S2 + prev[1]);
            } else if (m == 33) {
                v = cumA + prev[32] + prev[33];
            } else {
                const float w = ex2f(ELT4(qA, j & 3) * NC2);
                v = fmaf(w, cumA, w * prev[m - 1]);
            }
            cumPA = cumA;
            cumA  = v;
        }
    }
    prev[33] = wpend;                             // B's m=33 (set at t=34)
}

__global__ void __launch_bounds__(32)
otam_kernel(const float* __restrict__ dists, float* __restrict__ out) {
    extern __shared__ float smem[];
    const int lane = threadIdx.x;
    const int pw   = blockIdx.x * PPW;            // 1250 * 32 == 40000 exactly

    const unsigned int smem_u32 = (unsigned int)__cvta_generic_to_shared(smem);

    // Stage s = rows [8s .. 8s+7] of this warp's 32 problems: 1KB contiguous
    // per problem, issued as 2 consecutive 512B warp-level cp.asyncs.
    auto prefetch = [&](int s) {
        const unsigned int bu = smem_u32 + (unsigned int)((s & 1) * BUF_WORDS_1) * 4u;
        #pragma unroll
        for (int it = 0; it < 64; it++) {
            const int idx = it * 32 + lane;
            const int q = idx >> 6;               // local problem 0..31
            const int c = idx & 63;               // float4 within 8-row chunk
            const float* g = dists + (size_t)(pw + q) * 1024 + s * 256 + c * 4;
            cp_async16(bu + (unsigned int)(q * CHUNK_WORDS + c * 4) * 4u, g);
        }
        asm volatile("cp.async.commit_group;\n" ::);
    };

    float prev[34];

    prefetch(0);
    prefetch(1);

    #pragma unroll 1
    for (int s = 0; s < 4; s++) {
        if (s < 3) { asm volatile("cp.async.wait_group 1;\n" ::); }
        else       { asm volatile("cp.async.wait_group 0;\n" ::); }
        __syncwarp();

        const float* ch = smem + (s & 1) * BUF_WORDS_1 + lane * CHUNK_WORDS;

        if (s == 0) {
            // row 0: E[m] = prod of w, anchored at 2^S
            float4 dq = *reinterpret_cast<const float4*>(ch);
            prev[0] = TWO_S;
            prev[1] = ex2f(dq.x * NC2) * TWO_S;
            #pragma unroll
            for (int m = 2; m <= 32; m++) {
                const int j = m - 1;
                if ((j & 3) == 0) dq = *reinterpret_cast<const float4*>(ch + j);
                prev[m] = prev[m - 1] * ex2f(ELT4(dq, j & 3) * NC2);
            }
            prev[33] = prev[32];

            // row 1: single-row in-place pass (prevDiag register carries old row)
            {
                const float* dr = ch + 32;
                float4 dq1 = *reinterpret_cast<const float4*>(dr);
                float pd, cum;
                {   // m = 1
                    const float w = ex2f(dq1.x * NC2);
                    const float v = w * (TWO_S2 + prev[1]);
                    pd = prev[1]; prev[1] = v; cum = v;
                }
                #pragma unroll
                for (int m = 2; m <= 32; m++) {
                    const int j = m - 1;
                    if ((j & 3) == 0) dq1 = *reinterpret_cast<const float4*>(dr + j);
                    const float w = ex2f(ELT4(dq1, j & 3) * NC2);
                    const float v = fmaf(w, cum, w * pd);   // left=cum, diag=old prev[m-1]
                    pd = prev[m]; prev[m] = v; cum = v;
                }
                prev[33] = cum + pd + prev[33];             // m=33: left+diag+above
            }
            // rows 2..7: three skewed row-pairs
            two_rows(ch + 64,  prev);
            two_rows(ch + 128, prev);
            two_rows(ch + 192, prev);
        } else {
            // rows 8s .. 8s+7: four skewed row-pairs
            two_rows(ch,       prev);
            two_rows(ch + 64,  prev);
            two_rows(ch + 128, prev);
            two_rows(ch + 192, prev);
        }

        __syncwarp();                             // lanes done with buffer (s&1)
        if (s + 2 < 4) prefetch(s + 2);           // refill the freed buffer
    }

    // v = S - log2(E); out = v * lambda*ln2
    out[pw + lane] = fmaf(-LLN2, lg2f(prev[33]), SLLN2);
}

extern "C" void kernel_launch(void* const* d_in, const int* in_sizes, int n_in,
                              void* d_out, int out_size) {
    const float* dists = (const float*)d_in[0];
    float* out = (float*)d_out;
    const int blocks = QTOT / PPW;                     // 1250
    const size_t shmem = SMEM_WORDS * sizeof(float);   // 66560 B
    cudaFuncSetAttribute(otam_kernel, cudaFuncAttributeMaxDynamicSharedMemorySize,
                         (int)shmem);
    otam_kernel<<<blocks, 32, shmem>>>(dists, out);
}

// round 13
// speedup vs baseline: 1.1040x; 1.1040x over previous
#include <cuda_runtime.h>
#include <cuda_bf16.h>
#include <cstdint>

// OTAM cumulative soft-min DP.  dists: [200,200,32,32] f32 -> out [200,200] f32.
// lambda = 0.5.  Exp-domain: E(l,m) = 2^(S - v(l,m)/(lambda*ln2)), S = 96.
//   interior: E = w*(left + diag),  w = 2^(-d*C2)   (one FFMA on-chain)
//   m==1:     E = w*(2^(S+1) + above)
//   m==33:    E = left + diag + above               (d=0 -> w=1)
//   row 0:    E[m] = E[m-1]*w_m,  E[33] = E[32]
//   out = lambda*ln2 * (S - log2(E(31,33)))
//
// Round-13: TRIPLE-buffered 2-row stages with prefetch-ahead. During every
// compute window each warp keeps 2 cp.async groups (17KB) in flight instead
// of 1 (8.5KB): wait(<=2) -> compute s -> prefetch(s+3) into the freed buffer.
// 26.1KB smem/CTA -> 8 one-warp CTAs/SM, grid 1250 ~ full residency.

#define QTOT 40000
#define PPW 32                     // problems per warp (= per block)
#define CHUNK_WORDS 68             // 2 rows * 32 floats + 4 pad
#define BUF_WORDS_1 (PPW * CHUNK_WORDS)    // 2176 floats = 8704 B
#define SMEM_WORDS (3 * BUF_WORDS_1)       // 6528 floats = 26112 B

__device__ __forceinline__ float ex2f(float x) {
    float y; asm("ex2.approx.f32 %0, %1;" : "=f"(y) : "f"(x)); return y;
}
__device__ __forceinline__ float lg2f(float x) {
    float y; asm("lg2.approx.f32 %0, %1;" : "=f"(y) : "f"(x)); return y;
}
__device__ __forceinline__ void cp_async16(unsigned int dst, const void* src) {
    asm volatile("cp.async.cg.shared.global [%0], [%1], 16;\n"
                 :: "r"(dst), "l"(src) : "memory");
}

#define ELT4(v, k) ((k)==0 ? (v).x : ((k)==1 ? (v).y : ((k)==2 ? (v).z : (v).w)))

#define NC2    (-2.8853900817779268f)   // -1/(lambda*ln2)
#define LLN2   (0.34657359027997264f)   // lambda*ln2
#define TWO_S  (7.922816251426434e28f)  // 2^96
#define TWO_S2 (1.5845632502852868e29f) // 2^97
#define SLLN2  (33.271064666877374f)    // 96 * lambda*ln2

// Two skewed rows (A above B, B one column behind), exp domain, with a
// one-step-delayed prev[] write so the in-place update is hazard-free.
__device__ __forceinline__ void two_rows(const float* __restrict__ ch, float* prev) {
    const float* dA = ch;        // upper row's 32 d-values
    const float* dB = ch + 32;   // lower row
    float4 qA, qB;
    float cumA = TWO_S, cumPA = TWO_S, cumB = TWO_S;
    float wpend = 0.0f;

    #pragma unroll
    for (int t = 1; t <= 34; t++) {
        if (t >= 3) prev[t - 2] = wpend;          // delayed write of B's col t-2

        if (t >= 2) {                             // row B: m = t-1
            const int m = t - 1, j = m - 1;
            if (j < 32 && (j & 3) == 0) qB = *reinterpret_cast<const float4*>(dB + j);
            float v;
            if (m == 1) {
                const float w = ex2f(qB.x * NC2);
                v = w * (TWO_S2 + cumA);          // left=diag=2^S, above=v(A,1)
            } else if (m == 33) {
                v = cumB + cumPA + cumA;          // left + diag + above, w=1
            } else {
                const float w = ex2f(ELT4(qB, j & 3) * NC2);
                v = fmaf(w, cumB, w * cumPA);
            }
            wpend = v;
            cumB  = v;
        }

        if (t <= 33) {                            // row A: m = t
            const int m = t, j = m - 1;
            if ((j & 3) == 0) qA = *reinterpret_cast<const float4*>(dA + j);
            float v;
            if (m == 1) {
                const float w = ex2f(qA.x * NC2);
                v = w * (TWO_S2 + prev[1]);
            } else if (m == 33) {
                v = cumA + prev[32] + prev[33];
            } else {
                const float w = ex2f(ELT4(qA, j & 3) * NC2);
                v = fmaf(w, cumA, w * prev[m - 1]);
            }
            cumPA = cumA;
            cumA  = v;
        }
    }
    prev[33] = wpend;                             // B's m=33 (set at t=34)
}

__global__ void __launch_bounds__(32)
otam_kernel(const float* __restrict__ dists, float* __restrict__ out) {
    extern __shared__ float smem[];
    const int lane = threadIdx.x;
    const int pw   = blockIdx.x * PPW;            // 1250 * 32 == 40000 exactly

    const unsigned int smem_u32 = (unsigned int)__cvta_generic_to_shared(smem);

    // Stage s = rows {2s, 2s+1} of this warp's 32 problems (64 floats each),
    // coalesced 16B cp.asyncs into buffer (s % 3).
    auto prefetch = [&](int s) {
        const unsigned int bu = smem_u32 + (unsigned int)((s % 3) * BUF_WORDS_1) * 4u;
        #pragma unroll
        for (int it = 0; it < 16; it++) {
            const int idx = it * 32 + lane;
            const int q = idx >> 4;               // local problem 0..31
            const int c = idx & 15;               // float4 within 2-row chunk
            const float* g = dists + (size_t)(pw + q) * 1024 + s * 64 + c * 4;
            cp_async16(bu + (unsigned int)(q * CHUNK_WORDS + c * 4) * 4u, g);
        }
        asm volatile("cp.async.commit_group;\n" ::);
    };

    float prev[34];

    prefetch(0);
    prefetch(1);
    prefetch(2);

    #pragma unroll 1
    for (int s = 0; s < 16; s++) {
        // Drain exactly down to "group s complete": groups issued beyond s
        // number min(15-s, 2).
        if (s <= 13)      { asm volatile("cp.async.wait_group 2;\n" ::); }
        else if (s == 14) { asm volatile("cp.async.wait_group 1;\n" ::); }
        else              { asm volatile("cp.async.wait_group 0;\n" ::); }
        __syncwarp();

        const float* ch = smem + (s % 3) * BUF_WORDS_1 + lane * CHUNK_WORDS;

        if (s == 0) {
            // row 0: E[m] = prod of w, anchored at 2^S
            float4 dq = *reinterpret_cast<const float4*>(ch);
            prev[0] = TWO_S;
            prev[1] = ex2f(dq.x * NC2) * TWO_S;
            #pragma unroll
            for (int m = 2; m <= 32; m++) {
                const int j = m - 1;
                if ((j & 3) == 0) dq = *reinterpret_cast<const float4*>(ch + j);
                prev[m] = prev[m - 1] * ex2f(ELT4(dq, j & 3) * NC2);
            }
            prev[33] = prev[32];

            // row 1: single-row in-place pass (prevDiag register carries old row)
            {
                const float* dr = ch + 32;
                float4 dq1 = *reinterpret_cast<const float4*>(dr);
                float pd, cum;
                {   // m = 1
                    const float w = ex2f(dq1.x * NC2);
                    const float v = w * (TWO_S2 + prev[1]);
                    pd = prev[1]; prev[1] = v; cum = v;
                }
                #pragma unroll
                for (int m = 2; m <= 32; m++) {
                    const int j = m - 1;
                    if ((j & 3) == 0) dq1 = *reinterpret_cast<const float4*>(dr + j);
                    const float w = ex2f(ELT4(dq1, j & 3) * NC2);
                    const float v = fmaf(w, cum, w * pd);   // left=cum, diag=old prev[m-1]
                    pd = prev[m]; prev[m] = v; cum = v;
                }
                prev[33] = cum + pd + prev[33];             // m=33: left+diag+above
            }
        } else {
            two_rows(ch, prev);                   // rows 2s, 2s+1
        }

        __syncwarp();                             // lanes done with buffer (s%3)
        if (s + 3 < 16) prefetch(s + 3);          // refill the freed buffer
    }

    // v = S - log2(E); out = v * lambda*ln2
    out[pw + lane] = fmaf(-LLN2, lg2f(prev[33]), SLLN2);
}

extern "C" void kernel_launch(void* const* d_in, const int* in_sizes, int n_in,
                              void* d_out, int out_size) {
    const float* dists = (const float*)d_in[0];
    float* out = (float*)d_out;
    const int blocks = QTOT / PPW;                     // 1250
    const size_t shmem = SMEM_WORDS * sizeof(float);   // 26112 B
    cudaFuncSetAttribute(otam_kernel, cudaFuncAttributeMaxDynamicSharedMemorySize,
                         (int)shmem);
    otam_kernel<<<blocks, 32, shmem>>>(dists, out);
}

// round 15
// speedup vs baseline: 1.2210x; 1.1060x over previous
#include <cuda_runtime.h>
#include <cuda_bf16.h>
#include <cstdint>

// OTAM cumulative soft-min DP.  dists: [200,200,32,32] f32 -> out [200,200] f32.
// lambda = 0.5.  Exp-domain: E(l,m) = 2^(S - v(l,m)/(lambda*ln2)), S = 96.
//   interior: E = w*(left + diag),  w = 2^(-d*C2)   (one FFMA on-chain)
//   m==1:     E = w*(2^(S+1) + above)
//   m==33:    E = left + diag + above               (d=0 -> w=1)
//   row 0:    E[m] = E[m-1]*w_m,  E[33] = E[32]
//   out = lambda*ln2 * (S - log2(E(31,33)))
//
// Round-14: 1-ROW stages x 4 buffers. 18.4KB smem/CTA keeps 12 one-warp
// CTAs/SM (full grid residency - the R13 lesson), while the 4-deep ring gives
// 3 cp.async groups (12KB) in flight during every compute window and 32
// fine-grained stages to de-convoy the chip-level DRAM request stream.
// Compute = one in-place single-row pass per stage (pd-register carry).

#define QTOT 40000
#define PPW 32                     // problems per warp (= per block)
#define CHUNK_WORDS 36             // 1 row: 32 floats + 4 pad (9 f4 = 1 mod 8)
#define BUF_WORDS_1 (PPW * CHUNK_WORDS)    // 1152 floats = 4608 B
#define NBUF 4
#define SMEM_WORDS (NBUF * BUF_WORDS_1)    // 4608 floats = 18432 B

__device__ __forceinline__ float ex2f(float x) {
    float y; asm("ex2.approx.f32 %0, %1;" : "=f"(y) : "f"(x)); return y;
}
__device__ __forceinline__ float lg2f(float x) {
    float y; asm("lg2.approx.f32 %0, %1;" : "=f"(y) : "f"(x)); return y;
}
__device__ __forceinline__ void cp_async16(unsigned int dst, const void* src) {
    asm volatile("cp.async.cg.shared.global [%0], [%1], 16;\n"
                 :: "r"(dst), "l"(src) : "memory");
}

#define ELT4(v, k) ((k)==0 ? (v).x : ((k)==1 ? (v).y : ((k)==2 ? (v).z : (v).w)))

#define NC2    (-2.8853900817779268f)   // -1/(lambda*ln2)
#define LLN2   (0.34657359027997264f)   // lambda*ln2
#define TWO_S  (7.922816251426434e28f)  // 2^96
#define TWO_S2 (1.5845632502852868e29f) // 2^97
#define SLLN2  (33.271064666877374f)    // 96 * lambda*ln2

__global__ void __launch_bounds__(32)
otam_kernel(const float* __restrict__ dists, float* __restrict__ out) {
    extern __shared__ float smem[];
    const int lane = threadIdx.x;
    const int pw   = blockIdx.x * PPW;            // 1250 * 32 == 40000 exactly

    const unsigned int smem_u32 = (unsigned int)__cvta_generic_to_shared(smem);

    // Stage s = row s of this warp's 32 problems (32 floats = 128B each),
    // 8 coalesced 512B warp-level cp.asyncs into buffer (s % NBUF).
    auto prefetch = [&](int s) {
        const unsigned int bu = smem_u32 + (unsigned int)((s % NBUF) * BUF_WORDS_1) * 4u;
        #pragma unroll
        for (int it = 0; it < 8; it++) {
            const int idx = it * 32 + lane;
            const int q = idx >> 3;               // local problem 0..31
            const int c = idx & 7;                // float4 within row chunk
            const float* g = dists + (size_t)(pw + q) * 1024 + s * 32 + c * 4;
            cp_async16(bu + (unsigned int)(q * CHUNK_WORDS + c * 4) * 4u, g);
        }
        asm volatile("cp.async.commit_group;\n" ::);
    };

    float prev[34];

    prefetch(0);
    prefetch(1);
    prefetch(2);
    prefetch(3);

    #pragma unroll 1
    for (int s = 0; s < 32; s++) {
        // groups issued so far: min(32, s+4); need group s complete
        // -> allowed pending = min(32, s+4) - (s+1)
        if (s <= 28)      { asm volatile("cp.async.wait_group 3;\n" ::); }
        else if (s == 29) { asm volatile("cp.async.wait_group 2;\n" ::); }
        else if (s == 30) { asm volatile("cp.async.wait_group 1;\n" ::); }
        else              { asm volatile("cp.async.wait_group 0;\n" ::); }
        __syncwarp();

        const float* dr = smem + (s % NBUF) * BUF_WORDS_1 + lane * CHUNK_WORDS;

        if (s == 0) {
            // row 0: E[m] = prod of w, anchored at 2^S
            float4 dq = *reinterpret_cast<const float4*>(dr);
            prev[0] = TWO_S;
            prev[1] = ex2f(dq.x * NC2) * TWO_S;
            #pragma unroll
            for (int m = 2; m <= 32; m++) {
                const int j = m - 1;
                if ((j & 3) == 0) dq = *reinterpret_cast<const float4*>(dr + j);
                prev[m] = prev[m - 1] * ex2f(ELT4(dq, j & 3) * NC2);
            }
            prev[33] = prev[32];
        } else {
            // row s: in-place single pass; pd carries the OLD prev[m] value
            float4 dq = *reinterpret_cast<const float4*>(dr);
            float pd, cum;
            {   // m = 1
                const float w = ex2f(dq.x * NC2);
                const float v = w * (TWO_S2 + prev[1]);   // left=diag=2^S, above
                pd = prev[1]; prev[1] = v; cum = v;
            }
            #pragma unroll
            for (int m = 2; m <= 32; m++) {
                const int j = m - 1;
                if ((j & 3) == 0) dq = *reinterpret_cast<const float4*>(dr + j);
                const float w = ex2f(ELT4(dq, j & 3) * NC2);
                const float v = fmaf(w, cum, w * pd);     // left=cum, diag=old prev[m-1]
                pd = prev[m]; prev[m] = v; cum = v;
            }
            prev[33] = cum + pd + prev[33];               // m=33: left+diag+above
        }

        __syncwarp();                             // lanes done with buffer (s%NBUF)
        if (s + 4 < 32) prefetch(s + 4);          // refill the freed buffer
    }

    // v = S - log2(E); out = v * lambda*ln2
    out[pw + lane] = fmaf(-LLN2, lg2f(prev[33]), SLLN2);
}

extern "C" void kernel_launch(void* const* d_in, const int* in_sizes, int n_in,
                              void* d_out, int out_size) {
    const float* dists = (const float*)d_in[0];
    float* out = (float*)d_out;
    const int blocks = QTOT / PPW;                     // 1250
    const size_t shmem = SMEM_WORDS * sizeof(float);   // 18432 B
    cudaFuncSetAttribute(otam_kernel, cudaFuncAttributeMaxDynamicSharedMemorySize,
                         (int)shmem);
    otam_kernel<<<blocks, 32, shmem>>>(dists, out);
}

// round 17
// speedup vs baseline: 1.2221x; 1.0009x over previous
#include <cuda_runtime.h>
#include <cuda_bf16.h>
#include <cstdint>

// OTAM cumulative soft-min DP.  dists: [200,200,32,32] f32 -> out [200,200] f32.
// lambda = 0.5.  Exp-domain: E(l,m) = 2^(S - v(l,m)/(lambda*ln2)), S = 96.
//   interior: E = w*(left + diag),  w = 2^(-d*C2)   (one FFMA on-chain)
//   m==1:     E = w*(2^(S+1) + above)
//   m==33:    E = left + diag + above               (d=0 -> w=1)
//   row 0:    E[m] = E[m-1]*w_m,  E[33] = E[32]
//   out = lambda*ln2 * (S - log2(E(31,33)))
//
// Round-16: best-known structure (R10/R11: 1250 one-warp CTAs, 2-row
// double-buffered cp.async stages, fully resident) + L2::256B PREFETCH hint
// on every cp.async. All reads are compulsory L2 misses; if the ~4.9TB/s
// plateau is the per-miss handling rate, halving distinct misses (256B fill
// granules on a perfectly sequential stream) should raise it.

#define QTOT 40000
#define PPW 32                     // problems per warp (= per block)
#define CHUNK_WORDS 68             // 2 rows * 32 floats + 4 pad
#define BUF_WORDS_1 (PPW * CHUNK_WORDS)    // 2176 floats = 8704 B
#define SMEM_WORDS (2 * BUF_WORDS_1)       // 4352 floats = 17408 B

__device__ __forceinline__ float ex2f(float x) {
    float y; asm("ex2.approx.f32 %0, %1;" : "=f"(y) : "f"(x)); return y;
}
__device__ __forceinline__ float lg2f(float x) {
    float y; asm("lg2.approx.f32 %0, %1;" : "=f"(y) : "f"(x)); return y;
}
__device__ __forceinline__ void cp_async16(unsigned int dst, const void* src) {
    asm volatile("cp.async.cg.shared.global.L2::256B [%0], [%1], 16;\n"
                 :: "r"(dst), "l"(src) : "memory");
}

#define ELT4(v, k) ((k)==0 ? (v).x : ((k)==1 ? (v).y : ((k)==2 ? (v).z : (v).w)))

#define NC2    (-2.8853900817779268f)   // -1/(lambda*ln2)
#define LLN2   (0.34657359027997264f)   // lambda*ln2
#define TWO_S  (7.922816251426434e28f)  // 2^96
#define TWO_S2 (1.5845632502852868e29f) // 2^97
#define SLLN2  (33.271064666877374f)    // 96 * lambda*ln2

// Two skewed rows (A above B, B one column behind), exp domain, with a
// one-step-delayed prev[] write so the in-place update is hazard-free.
__device__ __forceinline__ void two_rows(const float* __restrict__ ch, float* prev) {
    const float* dA = ch;        // upper row's 32 d-values
    const float* dB = ch + 32;   // lower row
    float4 qA, qB;
    float cumA = TWO_S, cumPA = TWO_S, cumB = TWO_S;
    float wpend = 0.0f;

    #pragma unroll
    for (int t = 1; t <= 34; t++) {
        if (t >= 3) prev[t - 2] = wpend;          // delayed write of B's col t-2

        if (t >= 2) {                             // row B: m = t-1
            const int m = t - 1, j = m - 1;
            if (j < 32 && (j & 3) == 0) qB = *reinterpret_cast<const float4*>(dB + j);
            float v;
            if (m == 1) {
                const float w = ex2f(qB.x * NC2);
                v = w * (TWO_S2 + cumA);          // left=diag=2^S, above=v(A,1)
            } else if (m == 33) {
                v = cumB + cumPA + cumA;          // left + diag + above, w=1
            } else {
                const float w = ex2f(ELT4(qB, j & 3) * NC2);
                v = fmaf(w, cumB, w * cumPA);
            }
            wpend = v;
            cumB  = v;
        }

        if (t <= 33) {                            // row A: m = t
            const int m = t, j = m - 1;
            if ((j & 3) == 0) qA = *reinterpret_cast<const float4*>(dA + j);
            float v;
            if (m == 1) {
                const float w = ex2f(qA.x * NC2);
                v = w * (TWO_S2 + prev[1]);
            } else if (m == 33) {
                v = cumA + prev[32] + prev[33];
            } else {
                const float w = ex2f(ELT4(qA, j & 3) * NC2);
                v = fmaf(w, cumA, w * prev[m - 1]);
            }
            cumPA = cumA;
            cumA  = v;
        }
    }
    prev[33] = wpend;                             // B's m=33 (set at t=34)
}

__global__ void __launch_bounds__(32)
otam_kernel(const float* __restrict__ dists, float* __restrict__ out) {
    extern __shared__ float smem[];
    const int lane = threadIdx.x;
    const int pw   = blockIdx.x * PPW;            // 1250 * 32 == 40000 exactly

    const unsigned int smem_u32 = (unsigned int)__cvta_generic_to_shared(smem);

    // Stage s = rows {2s, 2s+1} of this warp's 32 problems (64 floats each),
    // coalesced 16B cp.asyncs into buffer (s & 1).
    auto prefetch = [&](int s) {
        const unsigned int bu = smem_u32 + (unsigned int)((s & 1) * BUF_WORDS_1) * 4u;
        #pragma unroll
        for (int it = 0; it < 16; it++) {
            const int idx = it * 32 + lane;
            const int q = idx >> 4;               // local problem 0..31
            const int c = idx & 15;               // float4 within 2-row chunk
            const float* g = dists + (size_t)(pw + q) * 1024 + s * 64 + c * 4;
            cp_async16(bu + (unsigned int)(q * CHUNK_WORDS + c * 4) * 4u, g);
        }
        asm volatile("cp.async.commit_group;\n" ::);
    };

    float prev[34];

    prefetch(0);
    prefetch(1);

    #pragma unroll 1
    for (int s = 0; s < 16; s++) {
        if (s < 15) { asm volatile("cp.async.wait_group 1;\n" ::); }
        else        { asm volatile("cp.async.wait_group 0;\n" ::); }
        __syncwarp();

        const float* ch = smem + (s & 1) * BUF_WORDS_1 + lane * CHUNK_WORDS;

        if (s == 0) {
            // row 0: E[m] = prod of w, anchored at 2^S
            float4 dq = *reinterpret_cast<const float4*>(ch);
            prev[0] = TWO_S;
            prev[1] = ex2f(dq.x * NC2) * TWO_S;
            #pragma unroll
            for (int m = 2; m <= 32; m++) {
                const int j = m - 1;
                if ((j & 3) == 0) dq = *reinterpret_cast<const float4*>(ch + j);
                prev[m] = prev[m - 1] * ex2f(ELT4(dq, j & 3) * NC2);
            }
            prev[33] = prev[32];

            // row 1: single-row in-place pass (prevDiag register carries old row)
            {
                const float* dr = ch + 32;
                float4 dq1 = *reinterpret_cast<const float4*>(dr);
                float pd, cum;
                {   // m = 1
                    const float w = ex2f(dq1.x * NC2);
                    const float v = w * (TWO_S2 + prev[1]);
                    pd = prev[1]; prev[1] = v; cum = v;
                }
                #pragma unroll
                for (int m = 2; m <= 32; m++) {
                    const int j = m - 1;
                    if ((j & 3) == 0) dq1 = *reinterpret_cast<const float4*>(dr + j);
                    const float w = ex2f(ELT4(dq1, j & 3) * NC2);
                    const float v = fmaf(w, cum, w * pd);   // left=cum, diag=old prev[m-1]
                    pd = prev[m]; prev[m] = v; cum = v;
                }
                prev[33] = cum + pd + prev[33];             // m=33: left+diag+above
            }
        } else {
            two_rows(ch, prev);                   // rows 2s, 2s+1
        }

        __syncwarp();                             // lanes done with buffer (s&1)
        if (s + 2 < 16) prefetch(s + 2);          // refill the freed buffer
    }

    // v = S - log2(E); out = v * lambda*ln2
    out[pw + lane] = fmaf(-LLN2, lg2f(prev[33]), SLLN2);
}

extern "C" void kernel_launch(void* const* d_in, const int* in_sizes, int n_in,
                              void* d_out, int out_size) {
    const float* dists = (const float*)d_in[0];
    float* out = (float*)d_out;
    const int blocks = QTOT / PPW;                     // 1250
    const size_t shmem = SMEM_WORDS * sizeof(float);   // 17408 B
    cudaFuncSetAttribute(otam_kernel, cudaFuncAttributeMaxDynamicSharedMemorySize,
                         (int)shmem);
    otam_kernel<<<blocks, 32, shmem>>>(dists, out);
}